// round 12
// baseline (speedup 1.0000x reference)
#include <cuda_runtime.h>
#include <cuda_fp16.h>
#include <math.h>
#include <stdint.h>

#define ENCD   1024
#define BATCH  32
#define SEQ    2048
#define MTOT   (BATCH * SEQ)   // 65536
#define NTILES 8               // 1024/128 n-tiles
#define NSTG   32              // K stages of 32
#define NCHUNK 8               // k4 S-chunks

// Scratch (static device arrays: no allocation allowed).
__device__ __half g_ench[(size_t)MTOT * ENCD];   // fp16 copy of enc (128MB)
__device__ __half g_w1t[ENCD * ENCD];            // fp16 w1 TRANSPOSED [n][k]
__device__ float  g_q[BATCH * ENCD];
__device__ float  g_partials[NTILES * MTOT];
__device__ float  g_attn[MTOT];
__device__ float  g_ctx[NCHUNK][BATCH * ENCD];

// ---------------------------------------------------------------------------
__device__ __forceinline__ void mma_f16(float* d, const uint32_t* a, const uint32_t* b) {
    asm volatile(
        "mma.sync.aligned.m16n8k16.row.col.f32.f16.f16.f32 "
        "{%0,%1,%2,%3},{%4,%5,%6,%7},{%8,%9},{%0,%1,%2,%3};"
        : "+f"(d[0]), "+f"(d[1]), "+f"(d[2]), "+f"(d[3])
        : "r"(a[0]), "r"(a[1]), "r"(a[2]), "r"(a[3]), "r"(b[0]), "r"(b[1]));
}
#define LDSM4(r0, r1, r2, r3, addr)                                          \
    asm volatile("ldmatrix.sync.aligned.m8n8.x4.shared.b16 {%0,%1,%2,%3}, [%4];" \
                 : "=r"(r0), "=r"(r1), "=r"(r2), "=r"(r3) : "r"(addr))
__device__ __forceinline__ float tanh_fast(float x) {
    float xc = fminf(fmaxf(x, -9.0f), 9.0f);
    float y, r;
    asm("ex2.approx.f32 %0, %1;" : "=f"(y) : "f"(xc * 2.885390081777927f));
    asm("rcp.approx.f32 %0, %1;" : "=f"(r) : "f"(y + 1.0f));
    return (y - 1.0f) * r;
}
__device__ __forceinline__ uint32_t smem_u32(const void* p) {
    uint32_t a;
    asm("{ .reg .u64 t; cvta.to.shared.u64 t, %1; cvt.u32.u64 %0, t; }"
        : "=r"(a) : "l"(p));
    return a;
}
#define CP_ASYNC16(dst, src) \
    asm volatile("cp.async.cg.shared.global [%0], [%1], 16;" :: "r"(dst), "l"(src) : "memory")
#define CP_COMMIT()  asm volatile("cp.async.commit_group;" ::: "memory")
#define CP_WAIT2()   asm volatile("cp.async.wait_group 2;" ::: "memory")

// smem geometry (bytes). CTA tile 64(M) x 128(N).
// A stage: 64 m-rows x 80B; B stage: 128 n-rows x 80B. 80B row stride keeps
// every 8-lane ldmatrix phase on 32 distinct banks. 4-stage ring.
#define ASTG   5120
#define BSTG   10240
#define OFF_A  0
#define OFF_B  (4 * ASTG)            // 20480
#define OFF_QS (OFF_B + 4 * BSTG)    // 61440
#define OFF_VS (OFF_QS + 512)
#define OFF_SR (OFF_VS + 512)
#define SMTOT  (OFF_SR + 1024)       // 63488 -> 3 CTAs/SM
#define MT     64                    // CTA tile M

// ---------------------------------------------------------------------------
// K0a: enc -> fp16 copy. 8 floats/thread. grid 32768 x 256.
// ---------------------------------------------------------------------------
__global__ __launch_bounds__(256)
void k0_enc(const float* __restrict__ enc) {
    const size_t i = ((size_t)blockIdx.x * 256 + threadIdx.x) * 8;
    float4 f0 = *(const float4*)(enc + i);
    float4 f1 = *(const float4*)(enc + i + 4);
    __half2 h0 = __floats2half2_rn(f0.x, f0.y);
    __half2 h1 = __floats2half2_rn(f0.z, f0.w);
    __half2 h2 = __floats2half2_rn(f1.x, f1.y);
    __half2 h3 = __floats2half2_rn(f1.z, f1.w);
    uint4 u;
    u.x = *(uint32_t*)&h0; u.y = *(uint32_t*)&h1;
    u.z = *(uint32_t*)&h2; u.w = *(uint32_t*)&h3;
    *(uint4*)(g_ench + i) = u;
}

// K0b: w1 -> fp16 transposed [n][k]. 32x32 smem tiles. grid (32, 32).
__global__ __launch_bounds__(256)
void k0_w1t(const float* __restrict__ w1) {
    __shared__ float tl[32][33];
    const int k0 = blockIdx.y * 32, nb = blockIdx.x * 32;
    const int tx = threadIdx.x & 31, ty = threadIdx.x >> 5;   // ty 0..7
    #pragma unroll
    for (int i = 0; i < 32; i += 8)
        tl[ty + i][tx] = w1[(size_t)(k0 + ty + i) * ENCD + nb + tx];
    __syncthreads();
    #pragma unroll
    for (int i = 0; i < 32; i += 8)
        g_w1t[(size_t)(nb + ty + i) * ENCD + k0 + tx] = __float2half_rn(tl[tx][ty + i]);
}

// ---------------------------------------------------------------------------
// K1: q'[b][e] = dec[b]@w2 + b2 + b1
// ---------------------------------------------------------------------------
__global__ __launch_bounds__(256)
void k1_query(const float* __restrict__ dec, const float* __restrict__ w2,
              const float* __restrict__ b1, const float* __restrict__ b2) {
    __shared__ float sdec[ENCD];
    const int b = blockIdx.x;
    for (int i = threadIdx.x; i < ENCD; i += 256) sdec[i] = dec[b * ENCD + i];
    __syncthreads();
    float acc[4] = {0.f, 0.f, 0.f, 0.f};
    const int e0 = threadIdx.x;
    for (int d = 0; d < ENCD; d++) {
        const float dv = sdec[d];
        const float* wrow = w2 + (size_t)d * ENCD;
        #pragma unroll
        for (int c = 0; c < 4; c++) acc[c] += dv * wrow[e0 + 256 * c];
    }
    #pragma unroll
    for (int c = 0; c < 4; c++) {
        const int e = e0 + 256 * c;
        g_q[b * ENCD + e] = acc[c] + b1[e] + b2[e];
    }
}

// ---------------------------------------------------------------------------
// K2: fused score GEMM, fp16 mma.sync m16n8k16 + ldmatrix.x4,
// cp.async 4-stage ring (stage loop unrolled x4 -> immediate ring offsets).
// CTA tile 64x128, 8 warps 2(M)x4(N), warp tile 32x32 (acc=32 regs ->
// 3 CTAs/SM, 24 warps). grid (8, 1024), 256 threads.
// ---------------------------------------------------------------------------
__global__ __launch_bounds__(256, 3)
void k2_scores(const float* __restrict__ v) {
    extern __shared__ __align__(16) float smf[];
    const uint32_t sb = smem_u32(smf);
    float* qs   = smf + (OFF_QS >> 2);
    float* vs   = smf + (OFF_VS >> 2);
    float* sred = smf + (OFF_SR >> 2);

    const int nt = blockIdx.x, n0 = nt * 128;
    const int m0 = blockIdx.y * MT;
    const int b  = m0 / SEQ;
    const int t  = threadIdx.x;
    const int lane = t & 31, w = t >> 5;
    const int wm = w & 1, wn = w >> 1;      // warp grid 2(M) x 4(N)
    const int g = lane >> 2, c = lane & 3;

    if (t < 128) { qs[t] = g_q[b * ENCD + n0 + t]; vs[t] = v[n0 + t]; }

    // ldmatrix per-lane addressing.
    const int lrow  = ((lane >> 3) & 1) * 8 + (lane & 7);
    const int lkoff = (lane >> 4) * 16;
    const uint32_t aTile = sb + OFF_A + (wm * 32 + lrow) * 80 + lkoff;
    const uint32_t bTile = sb + OFF_B + (wn * 32 + lrow) * 80 + lkoff;

    // Producers. A: 64 rows x 4 chunks = 256 -> 1 chunk/thread.
    // B: 128 rows x 4 chunks = 512 -> 2 chunks/thread.
    const int r0 = t >> 2, j = t & 3;
    const __half* aS  = g_ench + (size_t)(m0 + r0) * ENCD + j * 8;
    const __half* bS0 = g_w1t + (size_t)(n0 + r0) * ENCD + j * 8;
    const __half* bS1 = g_w1t + (size_t)(n0 + r0 + 64) * ENCD + j * 8;
    const uint32_t aD  = sb + OFF_A + r0 * 80 + j * 16;
    const uint32_t bD0 = sb + OFF_B + r0 * 80 + j * 16;
    const uint32_t bD1 = sb + OFF_B + (r0 + 64) * 80 + j * 16;

    #define ISSUE(s, ring)                                                   \
        do {                                                                 \
            const int _ko = (s) * 32;                                        \
            CP_ASYNC16(aD  + (ring) * ASTG, aS  + _ko);                      \
            CP_ASYNC16(bD0 + (ring) * BSTG, bS0 + _ko);                      \
            CP_ASYNC16(bD1 + (ring) * BSTG, bS1 + _ko);                      \
        } while (0)

    float acc[2][4][4];
    #pragma unroll
    for (int mi = 0; mi < 2; mi++)
        #pragma unroll
        for (int ni = 0; ni < 4; ni++)
            #pragma unroll
            for (int r = 0; r < 4; r++) acc[mi][ni][r] = 0.f;

    ISSUE(0, 0); CP_COMMIT();
    ISSUE(1, 1); CP_COMMIT();

    for (int so = 0; so < NSTG; so += 4) {
        #pragma unroll
        for (int ss = 0; ss < 4; ss++) {        // ring index compile-time
            const int s = so + ss;
            if (s + 2 < NSTG) ISSUE(s + 2, (ss + 2) & 3);
            CP_COMMIT();
            CP_WAIT2();
            __syncthreads();

            #pragma unroll
            for (int kh = 0; kh < 2; kh++) {    // two k16 chunks per stage
                const uint32_t ka = ss * ASTG + kh * 32;
                const uint32_t kb = ss * BSTG + kh * 32;
                uint32_t af[2][4], bf[4][2];
                #pragma unroll
                for (int mi = 0; mi < 2; mi++)
                    LDSM4(af[mi][0], af[mi][1], af[mi][2], af[mi][3],
                          aTile + mi * 1280 + ka);
                // B x4 over an ni-pair: r0,r2 -> ni ; r1,r3 -> ni+1.
                LDSM4(bf[0][0], bf[1][0], bf[0][1], bf[1][1], bTile + kb);
                LDSM4(bf[2][0], bf[3][0], bf[2][1], bf[3][1], bTile + 1280 + kb);
                #pragma unroll
                for (int mi = 0; mi < 2; mi++)
                    #pragma unroll
                    for (int ni = 0; ni < 4; ni++)
                        mma_f16(acc[mi][ni], af[mi], bf[ni]);
            }
            __syncthreads();
        }
    }

    // Epilogue. C frag: c0=(g,2c), c1=(g,2c+1), c2=(g+8,2c), c3=(g+8,2c+1)
    float rs0[2], rs1[2];
    #pragma unroll
    for (int mi = 0; mi < 2; mi++) {
        float s0 = 0.f, s1 = 0.f;
        #pragma unroll
        for (int ni = 0; ni < 4; ni++) {
            const int n_ = wn * 32 + ni * 8 + c * 2;
            const float q0 = qs[n_], q1 = qs[n_ + 1];
            const float v0 = vs[n_], v1 = vs[n_ + 1];
            s0 += tanh_fast(acc[mi][ni][0] + q0) * v0
                + tanh_fast(acc[mi][ni][1] + q1) * v1;
            s1 += tanh_fast(acc[mi][ni][2] + q0) * v0
                + tanh_fast(acc[mi][ni][3] + q1) * v1;
        }
        s0 += __shfl_xor_sync(0xffffffffu, s0, 1);
        s0 += __shfl_xor_sync(0xffffffffu, s0, 2);
        s1 += __shfl_xor_sync(0xffffffffu, s1, 1);
        s1 += __shfl_xor_sync(0xffffffffu, s1, 2);
        rs0[mi] = s0; rs1[mi] = s1;
    }
    if (c == 0) {
        #pragma unroll
        for (int mi = 0; mi < 2; mi++) {
            sred[wn * MT + wm * 32 + mi * 16 + g]     = rs0[mi];
            sred[wn * MT + wm * 32 + mi * 16 + g + 8] = rs1[mi];
        }
    }
    __syncthreads();
    if (t < MT)
        g_partials[(size_t)nt * MTOT + m0 + t] =
            (sred[t] + sred[MT + t]) + (sred[2 * MT + t] + sred[3 * MT + t]);
}

// ---------------------------------------------------------------------------
// K3: sum NTILES partials (fixed order), softmax over S per batch.
// ---------------------------------------------------------------------------
__global__ __launch_bounds__(256)
void k3_softmax() {
    __shared__ float red[256];
    const int b = blockIdx.x, t = threadIdx.x;
    float sc[8];
    float mx = -1e30f;
    #pragma unroll
    for (int i = 0; i < 8; i++) {
        const int s = t + 256 * i;
        float v0 = 0.f;
        #pragma unroll
        for (int nt = 0; nt < NTILES; nt++)
            v0 += g_partials[(size_t)nt * MTOT + b * SEQ + s];
        sc[i] = v0;
        mx = fmaxf(mx, v0);
    }
    red[t] = mx; __syncthreads();
    for (int o = 128; o > 0; o >>= 1) {
        if (t < o) red[t] = fmaxf(red[t], red[t + o]);
        __syncthreads();
    }
    mx = red[0]; __syncthreads();
    float sum = 0.f;
    #pragma unroll
    for (int i = 0; i < 8; i++) { sc[i] = expf(sc[i] - mx); sum += sc[i]; }
    red[t] = sum; __syncthreads();
    for (int o = 128; o > 0; o >>= 1) {
        if (t < o) red[t] += red[t + o];
        __syncthreads();
    }
    const float inv = 1.f / red[0];
    #pragma unroll
    for (int i = 0; i < 8; i++)
        g_attn[b * SEQ + t + 256 * i] = sc[i] * inv;
}

// ---------------------------------------------------------------------------
// K4: partial context over S-chunks of 256, fp16 enc. grid (4, 32, 8).
// ---------------------------------------------------------------------------
__global__ __launch_bounds__(256)
void k4_context() {
    __shared__ float sat[256];
    const int b  = blockIdx.y;
    const int sc = blockIdx.z;
    const int e  = blockIdx.x * 256 + threadIdx.x;
    const int sbase = sc * 256;
    sat[threadIdx.x] = g_attn[b * SEQ + sbase + threadIdx.x];
    __syncthreads();
    const __half* ep = g_ench + ((size_t)b * SEQ + sbase) * ENCD + e;
    float a0 = 0, a1 = 0, a2 = 0, a3 = 0, a4 = 0, a5 = 0, a6 = 0, a7 = 0;
    for (int s = 0; s < 256; s += 8) {
        a0 += sat[s + 0] * __half2float(ep[(size_t)(s + 0) * ENCD]);
        a1 += sat[s + 1] * __half2float(ep[(size_t)(s + 1) * ENCD]);
        a2 += sat[s + 2] * __half2float(ep[(size_t)(s + 2) * ENCD]);
        a3 += sat[s + 3] * __half2float(ep[(size_t)(s + 3) * ENCD]);
        a4 += sat[s + 4] * __half2float(ep[(size_t)(s + 4) * ENCD]);
        a5 += sat[s + 5] * __half2float(ep[(size_t)(s + 5) * ENCD]);
        a6 += sat[s + 6] * __half2float(ep[(size_t)(s + 6) * ENCD]);
        a7 += sat[s + 7] * __half2float(ep[(size_t)(s + 7) * ENCD]);
    }
    g_ctx[sc][b * ENCD + e] = ((a0 + a1) + (a2 + a3)) + ((a4 + a5) + (a6 + a7));
}

__global__ __launch_bounds__(256)
void k5_reduce(float* __restrict__ out) {
    const int i = blockIdx.x * 256 + threadIdx.x;
    float s = 0.f;
    #pragma unroll
    for (int ch = 0; ch < NCHUNK; ch++) s += g_ctx[ch][i];
    out[i] = s;
}

// ---------------------------------------------------------------------------
extern "C" void kernel_launch(void* const* d_in, const int* in_sizes, int n_in,
                              void* d_out, int out_size) {
    const float* enc = (const float*)d_in[0];
    const float* dec = (const float*)d_in[1];
    const float* w1  = (const float*)d_in[2];
    const float* b1  = (const float*)d_in[3];
    const float* w2  = (const float*)d_in[4];
    const float* b2  = (const float*)d_in[5];
    const float* v   = (const float*)d_in[6];
    float* out = (float*)d_out;

    cudaFuncSetAttribute(k2_scores, cudaFuncAttributeMaxDynamicSharedMemorySize,
                         SMTOT);

    k0_enc<<<32768, 256>>>(enc);
    k0_w1t<<<dim3(32, 32), 256>>>(w1);
    k1_query<<<32, 256>>>(dec, w2, b1, b2);
    k2_scores<<<dim3(NTILES, MTOT / MT), 256, SMTOT>>>(v);
    k3_softmax<<<32, 256>>>();
    k4_context<<<dim3(4, 32, NCHUNK), 256>>>();
    k5_reduce<<<128, 256>>>(out);
}

// round 13
// speedup vs baseline: 1.1048x; 1.1048x over previous
#include <cuda_runtime.h>
#include <cuda_fp16.h>
#include <math.h>
#include <stdint.h>

#define ENCD   1024
#define BATCH  32
#define SEQ    2048
#define MTOT   (BATCH * SEQ)   // 65536
#define NTILES 8               // 1024/128 n-tiles
#define NSTG   16              // K stages of 64
#define NCHUNK 8               // k4 S-chunks

// Scratch (static device arrays: no allocation allowed).
__device__ __half g_ench[(size_t)MTOT * ENCD];   // fp16 copy of enc (128MB)
__device__ __half g_w1t[ENCD * ENCD];            // fp16 w1 TRANSPOSED [n][k]
__device__ float  g_q[BATCH * ENCD];
__device__ float  g_partials[NTILES * MTOT];
__device__ float  g_attn[MTOT];
__device__ float  g_ctx[NCHUNK][BATCH * ENCD];

// ---------------------------------------------------------------------------
__device__ __forceinline__ void mma_f16(float* d, const uint32_t* a, const uint32_t* b) {
    asm volatile(
        "mma.sync.aligned.m16n8k16.row.col.f32.f16.f16.f32 "
        "{%0,%1,%2,%3},{%4,%5,%6,%7},{%8,%9},{%0,%1,%2,%3};"
        : "+f"(d[0]), "+f"(d[1]), "+f"(d[2]), "+f"(d[3])
        : "r"(a[0]), "r"(a[1]), "r"(a[2]), "r"(a[3]), "r"(b[0]), "r"(b[1]));
}
#define LDSM4(r0, r1, r2, r3, addr)                                          \
    asm volatile("ldmatrix.sync.aligned.m8n8.x4.shared.b16 {%0,%1,%2,%3}, [%4];" \
                 : "=r"(r0), "=r"(r1), "=r"(r2), "=r"(r3) : "r"(addr))
__device__ __forceinline__ float tanh_fast(float x) {
    float xc = fminf(fmaxf(x, -9.0f), 9.0f);
    float y, r;
    asm("ex2.approx.f32 %0, %1;" : "=f"(y) : "f"(xc * 2.885390081777927f));
    asm("rcp.approx.f32 %0, %1;" : "=f"(r) : "f"(y + 1.0f));
    return (y - 1.0f) * r;
}
__device__ __forceinline__ uint32_t smem_u32(const void* p) {
    uint32_t a;
    asm("{ .reg .u64 t; cvta.to.shared.u64 t, %1; cvt.u32.u64 %0, t; }"
        : "=r"(a) : "l"(p));
    return a;
}
#define CP_ASYNC16(dst, src) \
    asm volatile("cp.async.cg.shared.global [%0], [%1], 16;" :: "r"(dst), "l"(src) : "memory")
#define CP_COMMIT()  asm volatile("cp.async.commit_group;" ::: "memory")
#define CP_WAIT1()   asm volatile("cp.async.wait_group 1;" ::: "memory")

// smem geometry (bytes). CTA tile 128(M) x 128(N), KC=64.
// Row = 64 fp16 = 128B data + 16B pad = 144B. ldmatrix phase banks:
// 36r mod 32 = 4r -> 8 disjoint 4-bank spans = all 32 banks, conflict-free.
#define ROWB   144
#define ASTG   (128 * ROWB)          // 18432
#define BSTG   (128 * ROWB)
#define OFF_A  0
#define OFF_B  (2 * ASTG)            // 36864
#define OFF_QS (OFF_B + 2 * BSTG)    // 73728
#define OFF_VS (OFF_QS + 512)
#define OFF_SR (OFF_VS + 512)
#define SMTOT  (OFF_SR + 2048)       // 76800 -> 2 CTAs/SM

// ---------------------------------------------------------------------------
// K0a: enc -> fp16 copy. 8 floats/thread. grid 32768 x 256.
// ---------------------------------------------------------------------------
__global__ __launch_bounds__(256)
void k0_enc(const float* __restrict__ enc) {
    const size_t i = ((size_t)blockIdx.x * 256 + threadIdx.x) * 8;
    float4 f0 = *(const float4*)(enc + i);
    float4 f1 = *(const float4*)(enc + i + 4);
    __half2 h0 = __floats2half2_rn(f0.x, f0.y);
    __half2 h1 = __floats2half2_rn(f0.z, f0.w);
    __half2 h2 = __floats2half2_rn(f1.x, f1.y);
    __half2 h3 = __floats2half2_rn(f1.z, f1.w);
    uint4 u;
    u.x = *(uint32_t*)&h0; u.y = *(uint32_t*)&h1;
    u.z = *(uint32_t*)&h2; u.w = *(uint32_t*)&h3;
    *(uint4*)(g_ench + i) = u;
}

// K0b: w1 -> fp16 transposed [n][k]. 32x32 smem tiles. grid (32, 32).
__global__ __launch_bounds__(256)
void k0_w1t(const float* __restrict__ w1) {
    __shared__ float tl[32][33];
    const int k0 = blockIdx.y * 32, nb = blockIdx.x * 32;
    const int tx = threadIdx.x & 31, ty = threadIdx.x >> 5;   // ty 0..7
    #pragma unroll
    for (int i = 0; i < 32; i += 8)
        tl[ty + i][tx] = w1[(size_t)(k0 + ty + i) * ENCD + nb + tx];
    __syncthreads();
    #pragma unroll
    for (int i = 0; i < 32; i += 8)
        g_w1t[(size_t)(nb + ty + i) * ENCD + k0 + tx] = __float2half_rn(tl[tx][ty + i]);
}

// ---------------------------------------------------------------------------
// K1: q'[b][e] = dec[b]@w2 + b2 + b1
// ---------------------------------------------------------------------------
__global__ __launch_bounds__(256)
void k1_query(const float* __restrict__ dec, const float* __restrict__ w2,
              const float* __restrict__ b1, const float* __restrict__ b2) {
    __shared__ float sdec[ENCD];
    const int b = blockIdx.x;
    for (int i = threadIdx.x; i < ENCD; i += 256) sdec[i] = dec[b * ENCD + i];
    __syncthreads();
    float acc[4] = {0.f, 0.f, 0.f, 0.f};
    const int e0 = threadIdx.x;
    for (int d = 0; d < ENCD; d++) {
        const float dv = sdec[d];
        const float* wrow = w2 + (size_t)d * ENCD;
        #pragma unroll
        for (int c = 0; c < 4; c++) acc[c] += dv * wrow[e0 + 256 * c];
    }
    #pragma unroll
    for (int c = 0; c < 4; c++) {
        const int e = e0 + 256 * c;
        g_q[b * ENCD + e] = acc[c] + b1[e] + b2[e];
    }
}

// ---------------------------------------------------------------------------
// K2: fused score GEMM, fp16 mma.sync m16n8k16 + ldmatrix.x4, KC=64 stages,
// depth-2 cp.async ring fully unrolled (all smem addrs immediate).
// CTA tile 128x128, 8 warps 2(M)x4(N), warp 64x32. grid (8, 512), 256 thr.
// ---------------------------------------------------------------------------
__global__ __launch_bounds__(256, 2)
void k2_scores(const float* __restrict__ v) {
    extern __shared__ __align__(16) float smf[];
    const uint32_t sb = smem_u32(smf);
    float* qs   = smf + (OFF_QS >> 2);
    float* vs   = smf + (OFF_VS >> 2);
    float* sred = smf + (OFF_SR >> 2);

    const int nt = blockIdx.x, n0 = nt * 128;
    const int m0 = blockIdx.y * 128;
    const int b  = m0 / SEQ;
    const int t  = threadIdx.x;
    const int lane = t & 31, w = t >> 5;
    const int wm = w & 1, wn = w >> 1;      // warp grid 2(M) x 4(N)
    const int g = lane >> 2, c = lane & 3;

    if (t < 128) { qs[t] = g_q[b * ENCD + n0 + t]; vs[t] = v[n0 + t]; }

    // ldmatrix per-lane addressing.
    const int lrow  = ((lane >> 3) & 1) * 8 + (lane & 7);
    const int lkoff = (lane >> 4) * 16;
    const uint32_t aTile = sb + OFF_A + (wm * 64 + lrow) * ROWB + lkoff;
    const uint32_t bTile = sb + OFF_B + (wn * 32 + lrow) * ROWB + lkoff;

    // Producers: per stage per matrix 128 rows x 128B = 1024 x 16B chunks,
    // 4/thread: rows r, r+32, r+64, r+96 (r = t>>3), j = t&7.
    const int r0 = t >> 3, j = t & 3; // note: j below uses t&7
    const int jj = t & 7;
    const __half* aS = g_ench + (size_t)(m0 + r0) * ENCD + jj * 8;
    const __half* bS = g_w1t + (size_t)(n0 + r0) * ENCD + jj * 8;
    const uint32_t aD = sb + OFF_A + r0 * ROWB + jj * 16;
    const uint32_t bD = sb + OFF_B + r0 * ROWB + jj * 16;
    const size_t rstep = (size_t)32 * ENCD;   // +32 rows in gmem

    #define ISSUE(s, ring)                                                   \
        do {                                                                 \
            const int _ko = (s) * 64;                                        \
            CP_ASYNC16(aD + (ring) * ASTG,              aS + _ko);           \
            CP_ASYNC16(aD + (ring) * ASTG + 32 * ROWB,  aS + rstep + _ko);   \
            CP_ASYNC16(aD + (ring) * ASTG + 64 * ROWB,  aS + 2 * rstep + _ko); \
            CP_ASYNC16(aD + (ring) * ASTG + 96 * ROWB,  aS + 3 * rstep + _ko); \
            CP_ASYNC16(bD + (ring) * BSTG,              bS + _ko);           \
            CP_ASYNC16(bD + (ring) * BSTG + 32 * ROWB,  bS + rstep + _ko);   \
            CP_ASYNC16(bD + (ring) * BSTG + 64 * ROWB,  bS + 2 * rstep + _ko); \
            CP_ASYNC16(bD + (ring) * BSTG + 96 * ROWB,  bS + 3 * rstep + _ko); \
        } while (0)

    float acc[4][4][4];
    #pragma unroll
    for (int mi = 0; mi < 4; mi++)
        #pragma unroll
        for (int ni = 0; ni < 4; ni++)
            #pragma unroll
            for (int r = 0; r < 4; r++) acc[mi][ni][r] = 0.f;

    ISSUE(0, 0); CP_COMMIT();

    for (int so = 0; so < NSTG; so += 2) {
        #pragma unroll
        for (int ss = 0; ss < 2; ss++) {        // ring index compile-time
            const int s = so + ss;
            if (s + 1 < NSTG) ISSUE(s + 1, ss ^ 1);
            CP_COMMIT();
            CP_WAIT1();                          // stage s landed
            __syncthreads();

            #pragma unroll
            for (int kh = 0; kh < 4; kh++) {     // four k16 chunks per stage
                const uint32_t ka = ss * ASTG + kh * 32;
                const uint32_t kb = ss * BSTG + kh * 32;
                uint32_t af[4][4], bf[4][2];
                #pragma unroll
                for (int mi = 0; mi < 4; mi++)
                    LDSM4(af[mi][0], af[mi][1], af[mi][2], af[mi][3],
                          aTile + mi * 16 * ROWB + ka);
                // B x4 over an ni-pair: r0,r2 -> ni ; r1,r3 -> ni+1.
                LDSM4(bf[0][0], bf[1][0], bf[0][1], bf[1][1], bTile + kb);
                LDSM4(bf[2][0], bf[3][0], bf[2][1], bf[3][1],
                      bTile + 16 * ROWB + kb);
                #pragma unroll
                for (int mi = 0; mi < 4; mi++)
                    #pragma unroll
                    for (int ni = 0; ni < 4; ni++)
                        mma_f16(acc[mi][ni], af[mi], bf[ni]);
            }
            __syncthreads();                     // all reads done before reuse
        }
    }

    // Epilogue. C frag: c0=(g,2c), c1=(g,2c+1), c2=(g+8,2c), c3=(g+8,2c+1)
    float rs0[4], rs1[4];
    #pragma unroll
    for (int mi = 0; mi < 4; mi++) {
        float s0 = 0.f, s1 = 0.f;
        #pragma unroll
        for (int ni = 0; ni < 4; ni++) {
            const int n_ = wn * 32 + ni * 8 + c * 2;
            const float q0 = qs[n_], q1 = qs[n_ + 1];
            const float v0 = vs[n_], v1 = vs[n_ + 1];
            s0 += tanh_fast(acc[mi][ni][0] + q0) * v0
                + tanh_fast(acc[mi][ni][1] + q1) * v1;
            s1 += tanh_fast(acc[mi][ni][2] + q0) * v0
                + tanh_fast(acc[mi][ni][3] + q1) * v1;
        }
        s0 += __shfl_xor_sync(0xffffffffu, s0, 1);
        s0 += __shfl_xor_sync(0xffffffffu, s0, 2);
        s1 += __shfl_xor_sync(0xffffffffu, s1, 1);
        s1 += __shfl_xor_sync(0xffffffffu, s1, 2);
        rs0[mi] = s0; rs1[mi] = s1;
    }
    if (c == 0) {
        #pragma unroll
        for (int mi = 0; mi < 4; mi++) {
            sred[wn * 128 + wm * 64 + mi * 16 + g]     = rs0[mi];
            sred[wn * 128 + wm * 64 + mi * 16 + g + 8] = rs1[mi];
        }
    }
    __syncthreads();
    if (t < 128)
        g_partials[(size_t)nt * MTOT + m0 + t] =
            (sred[t] + sred[128 + t]) + (sred[256 + t] + sred[384 + t]);
}

// ---------------------------------------------------------------------------
// K3: sum NTILES partials (fixed order), softmax over S per batch.
// ---------------------------------------------------------------------------
__global__ __launch_bounds__(256)
void k3_softmax() {
    __shared__ float red[256];
    const int b = blockIdx.x, t = threadIdx.x;
    float sc[8];
    float mx = -1e30f;
    #pragma unroll
    for (int i = 0; i < 8; i++) {
        const int s = t + 256 * i;
        float v0 = 0.f;
        #pragma unroll
        for (int nt = 0; nt < NTILES; nt++)
            v0 += g_partials[(size_t)nt * MTOT + b * SEQ + s];
        sc[i] = v0;
        mx = fmaxf(mx, v0);
    }
    red[t] = mx; __syncthreads();
    for (int o = 128; o > 0; o >>= 1) {
        if (t < o) red[t] = fmaxf(red[t], red[t + o]);
        __syncthreads();
    }
    mx = red[0]; __syncthreads();
    float sum = 0.f;
    #pragma unroll
    for (int i = 0; i < 8; i++) { sc[i] = expf(sc[i] - mx); sum += sc[i]; }
    red[t] = sum; __syncthreads();
    for (int o = 128; o > 0; o >>= 1) {
        if (t < o) red[t] += red[t + o];
        __syncthreads();
    }
    const float inv = 1.f / red[0];
    #pragma unroll
    for (int i = 0; i < 8; i++)
        g_attn[b * SEQ + t + 256 * i] = sc[i] * inv;
}

// ---------------------------------------------------------------------------
// K4: partial context over S-chunks of 256, fp16 enc. grid (4, 32, 8).
// ---------------------------------------------------------------------------
__global__ __launch_bounds__(256)
void k4_context() {
    __shared__ float sat[256];
    const int b  = blockIdx.y;
    const int sc = blockIdx.z;
    const int e  = blockIdx.x * 256 + threadIdx.x;
    const int sbase = sc * 256;
    sat[threadIdx.x] = g_attn[b * SEQ + sbase + threadIdx.x];
    __syncthreads();
    const __half* ep = g_ench + ((size_t)b * SEQ + sbase) * ENCD + e;
    float a0 = 0, a1 = 0, a2 = 0, a3 = 0, a4 = 0, a5 = 0, a6 = 0, a7 = 0;
    for (int s = 0; s < 256; s += 8) {
        a0 += sat[s + 0] * __half2float(ep[(size_t)(s + 0) * ENCD]);
        a1 += sat[s + 1] * __half2float(ep[(size_t)(s + 1) * ENCD]);
        a2 += sat[s + 2] * __half2float(ep[(size_t)(s + 2) * ENCD]);
        a3 += sat[s + 3] * __half2float(ep[(size_t)(s + 3) * ENCD]);
        a4 += sat[s + 4] * __half2float(ep[(size_t)(s + 4) * ENCD]);
        a5 += sat[s + 5] * __half2float(ep[(size_t)(s + 5) * ENCD]);
        a6 += sat[s + 6] * __half2float(ep[(size_t)(s + 6) * ENCD]);
        a7 += sat[s + 7] * __half2float(ep[(size_t)(s + 7) * ENCD]);
    }
    g_ctx[sc][b * ENCD + e] = ((a0 + a1) + (a2 + a3)) + ((a4 + a5) + (a6 + a7));
}

__global__ __launch_bounds__(256)
void k5_reduce(float* __restrict__ out) {
    const int i = blockIdx.x * 256 + threadIdx.x;
    float s = 0.f;
    #pragma unroll
    for (int ch = 0; ch < NCHUNK; ch++) s += g_ctx[ch][i];
    out[i] = s;
}

// ---------------------------------------------------------------------------
extern "C" void kernel_launch(void* const* d_in, const int* in_sizes, int n_in,
                              void* d_out, int out_size) {
    const float* enc = (const float*)d_in[0];
    const float* dec = (const float*)d_in[1];
    const float* w1  = (const float*)d_in[2];
    const float* b1  = (const float*)d_in[3];
    const float* w2  = (const float*)d_in[4];
    const float* b2  = (const float*)d_in[5];
    const float* v   = (const float*)d_in[6];
    float* out = (float*)d_out;

    cudaFuncSetAttribute(k2_scores, cudaFuncAttributeMaxDynamicSharedMemorySize,
                         SMTOT);

    k0_enc<<<32768, 256>>>(enc);
    k0_w1t<<<dim3(32, 32), 256>>>(w1);
    k1_query<<<32, 256>>>(dec, w2, b1, b2);
    k2_scores<<<dim3(NTILES, 512), 256, SMTOT>>>(v);
    k3_softmax<<<32, 256>>>();
    k4_context<<<dim3(4, 32, NCHUNK), 256>>>();
    k5_reduce<<<128, 256>>>(out);
}

// round 14
// speedup vs baseline: 1.3398x; 1.2127x over previous
#include <cuda_runtime.h>
#include <cuda_fp16.h>
#include <math.h>
#include <stdint.h>

#define ENCD   1024
#define BATCH  32
#define SEQ    2048
#define MTOT   (BATCH * SEQ)   // 65536
#define NTILES 8               // 1024/128 n-tiles
#define NSTG   32              // K stages of 32
#define NCHUNK 8               // k4 S-chunks

// Scratch (static device arrays: no allocation allowed).
__device__ __half g_ench[(size_t)MTOT * ENCD];   // fp16 copy of enc (128MB)
__device__ __half g_w1t[ENCD * ENCD];            // fp16 w1 TRANSPOSED [n][k]
__device__ float  g_q[BATCH * ENCD];
__device__ float  g_partials[NTILES * MTOT];
__device__ float  g_attn[MTOT];
__device__ float  g_ctx[NCHUNK][BATCH * ENCD];

// ---------------------------------------------------------------------------
__device__ __forceinline__ void mma_f16(float* d, const uint32_t* a, const uint32_t* b) {
    asm volatile(
        "mma.sync.aligned.m16n8k16.row.col.f32.f16.f16.f32 "
        "{%0,%1,%2,%3},{%4,%5,%6,%7},{%8,%9},{%0,%1,%2,%3};"
        : "+f"(d[0]), "+f"(d[1]), "+f"(d[2]), "+f"(d[3])
        : "r"(a[0]), "r"(a[1]), "r"(a[2]), "r"(a[3]), "r"(b[0]), "r"(b[1]));
}
#define LDSM4(r0, r1, r2, r3, addr)                                          \
    asm volatile("ldmatrix.sync.aligned.m8n8.x4.shared.b16 {%0,%1,%2,%3}, [%4];" \
                 : "=r"(r0), "=r"(r1), "=r"(r2), "=r"(r3) : "r"(addr))
__device__ __forceinline__ float tanh_fast(float x) {
    float xc = fminf(fmaxf(x, -9.0f), 9.0f);
    float y, r;
    asm("ex2.approx.f32 %0, %1;" : "=f"(y) : "f"(xc * 2.885390081777927f));
    asm("rcp.approx.f32 %0, %1;" : "=f"(r) : "f"(y + 1.0f));
    return (y - 1.0f) * r;
}
__device__ __forceinline__ uint32_t smem_u32(const void* p) {
    uint32_t a;
    asm("{ .reg .u64 t; cvta.to.shared.u64 t, %1; cvt.u32.u64 %0, t; }"
        : "=r"(a) : "l"(p));
    return a;
}
#define CP_ASYNC16(dst, src) \
    asm volatile("cp.async.cg.shared.global [%0], [%1], 16;" :: "r"(dst), "l"(src) : "memory")
#define CP_COMMIT()  asm volatile("cp.async.commit_group;" ::: "memory")
#define CP_WAIT2()   asm volatile("cp.async.wait_group 2;" ::: "memory")

// smem geometry (bytes). A stage: 128 m-rows x 80B (64B = 32 fp16 + 16B pad).
// B stage: 128 n-rows x 80B. 80B stride -> each 8-lane ldmatrix phase hits
// all 32 banks exactly once. 4-stage ring.
#define ASTG   10240
#define BSTG   10240
#define OFF_A  0
#define OFF_B  (4 * ASTG)            // 40960
#define OFF_QS (OFF_B + 4 * BSTG)    // 81920
#define OFF_VS (OFF_QS + 512)
#define OFF_SR (OFF_VS + 512)
#define SMTOT  (OFF_SR + 2048)       // 84992

// Fused prep kernel block ranges.
#define NB_Q   128                   // query blocks (4 e-chunks x 32 batches)
#define NB_W1T 1024                  // w1 transpose blocks (32 x 32 tiles)
#define NB_ENC 32768                 // enc convert blocks
#define NB_PREP (NB_Q + NB_W1T + NB_ENC)

// ---------------------------------------------------------------------------
// K0: fused prep. Block-range dispatch over 3 independent jobs:
//  [0, 128): q'[b][e] = dec[b]@w2 + b2 + b1  (128 blocks: 4 e-chunks x 32 b)
//  [128, 1152): w1 -> fp16 transposed [n][k] (32x32 tiles)
//  [1152, 33920): enc -> fp16 copy (8 floats/thread)
// Small jobs ride inside the enc-convert's memory time instead of serializing.
// ---------------------------------------------------------------------------
__global__ __launch_bounds__(256)
void k0_prep(const float* __restrict__ enc, const float* __restrict__ w1,
             const float* __restrict__ dec, const float* __restrict__ w2,
             const float* __restrict__ b1, const float* __restrict__ b2) {
    __shared__ float sh[1056];
    const int id = blockIdx.x;
    const int t  = threadIdx.x;

    if (id < NB_Q) {
        // ---- query GEMV: block (bx, b), 256 outputs e = bx*256 + t.
        const int bx = id & 3, b = id >> 2;
        for (int i = t; i < ENCD; i += 256) sh[i] = dec[b * ENCD + i];
        __syncthreads();
        const int e = bx * 256 + t;
        float acc = 0.f;
        #pragma unroll 8
        for (int d = 0; d < ENCD; d++)
            acc += sh[d] * w2[(size_t)d * ENCD + e];
        g_q[b * ENCD + e] = acc + b1[e] + b2[e];
    } else if (id < NB_Q + NB_W1T) {
        // ---- w1 transpose tile: 32x32.
        const int tid = id - NB_Q;
        const int nb = (tid & 31) * 32, k0 = (tid >> 5) * 32;
        float (*tl)[33] = (float(*)[33])sh;
        const int tx = t & 31, ty = t >> 5;   // ty 0..7
        #pragma unroll
        for (int i = 0; i < 32; i += 8)
            tl[ty + i][tx] = w1[(size_t)(k0 + ty + i) * ENCD + nb + tx];
        __syncthreads();
        #pragma unroll
        for (int i = 0; i < 32; i += 8)
            g_w1t[(size_t)(nb + ty + i) * ENCD + k0 + tx] =
                __float2half_rn(tl[tx][ty + i]);
    } else {
        // ---- enc fp32 -> fp16, 8 floats/thread.
        const size_t i = ((size_t)(id - NB_Q - NB_W1T) * 256 + t) * 8;
        float4 f0 = *(const float4*)(enc + i);
        float4 f1 = *(const float4*)(enc + i + 4);
        __half2 h0 = __floats2half2_rn(f0.x, f0.y);
        __half2 h1 = __floats2half2_rn(f0.z, f0.w);
        __half2 h2 = __floats2half2_rn(f1.x, f1.y);
        __half2 h3 = __floats2half2_rn(f1.z, f1.w);
        uint4 u;
        u.x = *(uint32_t*)&h0; u.y = *(uint32_t*)&h1;
        u.z = *(uint32_t*)&h2; u.w = *(uint32_t*)&h3;
        *(uint4*)(g_ench + i) = u;
    }
}

// ---------------------------------------------------------------------------
// K2: fused score GEMM, fp16 mma.sync m16n8k16 + ldmatrix.x4 fragments,
// cp.async 4-stage pipeline (R11 configuration — best measured).
// CTA tile 128x128, 8 warps 2(M)x4(N), warp 64x32. grid (8, 512), 256 thr.
// ---------------------------------------------------------------------------
__global__ __launch_bounds__(256, 2)
void k2_scores(const float* __restrict__ v) {
    extern __shared__ __align__(16) float smf[];
    const uint32_t sb = smem_u32(smf);
    float* qs   = smf + (OFF_QS >> 2);
    float* vs   = smf + (OFF_VS >> 2);
    float* sred = smf + (OFF_SR >> 2);

    const int nt = blockIdx.x, n0 = nt * 128;
    const int m0 = blockIdx.y * 128;
    const int b  = m0 / SEQ;
    const int t  = threadIdx.x;
    const int lane = t & 31, w = t >> 5;
    const int wm = w & 1, wn = w >> 1;      // warp grid 2(M) x 4(N)
    const int g = lane >> 2, c = lane & 3;

    if (t < 128) { qs[t] = g_q[b * ENCD + n0 + t]; vs[t] = v[n0 + t]; }

    // ldmatrix per-lane addressing.
    const int lrow  = ((lane >> 3) & 1) * 8 + (lane & 7);
    const int lkoff = (lane >> 4) * 16;
    const uint32_t aTile = sb + OFF_A + (wm * 64 + lrow) * 80 + lkoff;
    const uint32_t bTile = sb + OFF_B + (wn * 32 + lrow) * 80 + lkoff;

    // Producers: per stage 128 rows x 64B per matrix = 512 chunks each;
    // thread handles chunks f = t, f = t+256: row = f>>2, j = f&3.
    const int r0 = t >> 2, r1 = r0 + 64, j = t & 3;
    const __half* aS0 = g_ench + (size_t)(m0 + r0) * ENCD + j * 8;
    const __half* aS1 = g_ench + (size_t)(m0 + r1) * ENCD + j * 8;
    const __half* bS0 = g_w1t + (size_t)(n0 + r0) * ENCD + j * 8;
    const __half* bS1 = g_w1t + (size_t)(n0 + r1) * ENCD + j * 8;
    const uint32_t aD0 = sb + OFF_A + r0 * 80 + j * 16;
    const uint32_t aD1 = sb + OFF_A + r1 * 80 + j * 16;
    const uint32_t bD0 = sb + OFF_B + r0 * 80 + j * 16;
    const uint32_t bD1 = sb + OFF_B + r1 * 80 + j * 16;

    #define ISSUE(s)                                                         \
        do {                                                                 \
            const uint32_t _rb = ((s) & 3) * ASTG;                           \
            const int _ko = (s) * 32;                                        \
            CP_ASYNC16(aD0 + _rb, aS0 + _ko);                                \
            CP_ASYNC16(aD1 + _rb, aS1 + _ko);                                \
            CP_ASYNC16(bD0 + _rb, bS0 + _ko);                                \
            CP_ASYNC16(bD1 + _rb, bS1 + _ko);                                \
        } while (0)

    float acc[4][4][4];
    #pragma unroll
    for (int mi = 0; mi < 4; mi++)
        #pragma unroll
        for (int ni = 0; ni < 4; ni++)
            #pragma unroll
            for (int r = 0; r < 4; r++) acc[mi][ni][r] = 0.f;

    ISSUE(0); CP_COMMIT();
    ISSUE(1); CP_COMMIT();

    for (int s = 0; s < NSTG; s++) {
        if (s + 2 < NSTG) ISSUE(s + 2);
        CP_COMMIT();
        CP_WAIT2();
        __syncthreads();

        const uint32_t stg = (s & 3) * ASTG;   // ASTG == BSTG
        #pragma unroll
        for (int kh = 0; kh < 2; kh++) {       // two k16 chunks per stage
            const uint32_t kb = stg + kh * 32;
            uint32_t af[4][4], bf[4][2];
            #pragma unroll
            for (int mi = 0; mi < 4; mi++)
                LDSM4(af[mi][0], af[mi][1], af[mi][2], af[mi][3],
                      aTile + mi * 1280 + kb);
            // B x4 over an ni-pair: r0,r2 -> ni ; r1,r3 -> ni+1.
            LDSM4(bf[0][0], bf[1][0], bf[0][1], bf[1][1], bTile + kb);
            LDSM4(bf[2][0], bf[3][0], bf[2][1], bf[3][1], bTile + 1280 + kb);
            #pragma unroll
            for (int mi = 0; mi < 4; mi++)
                #pragma unroll
                for (int ni = 0; ni < 4; ni++)
                    mma_f16(acc[mi][ni], af[mi], bf[ni]);
        }
    }

    // Epilogue. C frag: c0=(g,2c), c1=(g,2c+1), c2=(g+8,2c), c3=(g+8,2c+1)
    float rs0[4], rs1[4];
    #pragma unroll
    for (int mi = 0; mi < 4; mi++) {
        float s0 = 0.f, s1 = 0.f;
        #pragma unroll
        for (int ni = 0; ni < 4; ni++) {
            const int n_ = wn * 32 + ni * 8 + c * 2;
            const float q0 = qs[n_], q1 = qs[n_ + 1];
            const float v0 = vs[n_], v1 = vs[n_ + 1];
            s0 += tanh_fast(acc[mi][ni][0] + q0) * v0
                + tanh_fast(acc[mi][ni][1] + q1) * v1;
            s1 += tanh_fast(acc[mi][ni][2] + q0) * v0
                + tanh_fast(acc[mi][ni][3] + q1) * v1;
        }
        s0 += __shfl_xor_sync(0xffffffffu, s0, 1);
        s0 += __shfl_xor_sync(0xffffffffu, s0, 2);
        s1 += __shfl_xor_sync(0xffffffffu, s1, 1);
        s1 += __shfl_xor_sync(0xffffffffu, s1, 2);
        rs0[mi] = s0; rs1[mi] = s1;
    }
    if (c == 0) {
        #pragma unroll
        for (int mi = 0; mi < 4; mi++) {
            sred[wn * 128 + wm * 64 + mi * 16 + g]     = rs0[mi];
            sred[wn * 128 + wm * 64 + mi * 16 + g + 8] = rs1[mi];
        }
    }
    __syncthreads();
    if (t < 128)
        g_partials[(size_t)nt * MTOT + m0 + t] =
            (sred[t] + sred[128 + t]) + (sred[256 + t] + sred[384 + t]);
}

// ---------------------------------------------------------------------------
// K3: sum NTILES partials (fixed order), softmax over S per batch.
// ---------------------------------------------------------------------------
__global__ __launch_bounds__(256)
void k3_softmax() {
    __shared__ float red[256];
    const int b = blockIdx.x, t = threadIdx.x;
    float sc[8];
    float mx = -1e30f;
    #pragma unroll
    for (int i = 0; i < 8; i++) {
        const int s = t + 256 * i;
        float v0 = 0.f;
        #pragma unroll
        for (int nt = 0; nt < NTILES; nt++)
            v0 += g_partials[(size_t)nt * MTOT + b * SEQ + s];
        sc[i] = v0;
        mx = fmaxf(mx, v0);
    }
    red[t] = mx; __syncthreads();
    for (int o = 128; o > 0; o >>= 1) {
        if (t < o) red[t] = fmaxf(red[t], red[t + o]);
        __syncthreads();
    }
    mx = red[0]; __syncthreads();
    float sum = 0.f;
    #pragma unroll
    for (int i = 0; i < 8; i++) { sc[i] = expf(sc[i] - mx); sum += sc[i]; }
    red[t] = sum; __syncthreads();
    for (int o = 128; o > 0; o >>= 1) {
        if (t < o) red[t] += red[t + o];
        __syncthreads();
    }
    const float inv = 1.f / red[0];
    #pragma unroll
    for (int i = 0; i < 8; i++)
        g_attn[b * SEQ + t + 256 * i] = sc[i] * inv;
}

// ---------------------------------------------------------------------------
// K4: partial context over S-chunks of 256, fp16 enc. grid (4, 32, 8).
// ---------------------------------------------------------------------------
__global__ __launch_bounds__(256)
void k4_context() {
    __shared__ float sat[256];
    const int b  = blockIdx.y;
    const int sc = blockIdx.z;
    const int e  = blockIdx.x * 256 + threadIdx.x;
    const int sbase = sc * 256;
    sat[threadIdx.x] = g_attn[b * SEQ + sbase + threadIdx.x];
    __syncthreads();
    const __half* ep = g_ench + ((size_t)b * SEQ + sbase) * ENCD + e;
    float a0 = 0, a1 = 0, a2 = 0, a3 = 0, a4 = 0, a5 = 0, a6 = 0, a7 = 0;
    for (int s = 0; s < 256; s += 8) {
        a0 += sat[s + 0] * __half2float(ep[(size_t)(s + 0) * ENCD]);
        a1 += sat[s + 1] * __half2float(ep[(size_t)(s + 1) * ENCD]);
        a2 += sat[s + 2] * __half2float(ep[(size_t)(s + 2) * ENCD]);
        a3 += sat[s + 3] * __half2float(ep[(size_t)(s + 3) * ENCD]);
        a4 += sat[s + 4] * __half2float(ep[(size_t)(s + 4) * ENCD]);
        a5 += sat[s + 5] * __half2float(ep[(size_t)(s + 5) * ENCD]);
        a6 += sat[s + 6] * __half2float(ep[(size_t)(s + 6) * ENCD]);
        a7 += sat[s + 7] * __half2float(ep[(size_t)(s + 7) * ENCD]);
    }
    g_ctx[sc][b * ENCD + e] = ((a0 + a1) + (a2 + a3)) + ((a4 + a5) + (a6 + a7));
}

__global__ __launch_bounds__(256)
void k5_reduce(float* __restrict__ out) {
    const int i = blockIdx.x * 256 + threadIdx.x;
    float s = 0.f;
    #pragma unroll
    for (int ch = 0; ch < NCHUNK; ch++) s += g_ctx[ch][i];
    out[i] = s;
}

// ---------------------------------------------------------------------------
extern "C" void kernel_launch(void* const* d_in, const int* in_sizes, int n_in,
                              void* d_out, int out_size) {
    const float* enc = (const float*)d_in[0];
    const float* dec = (const float*)d_in[1];
    const float* w1  = (const float*)d_in[2];
    const float* b1  = (const float*)d_in[3];
    const float* w2  = (const float*)d_in[4];
    const float* b2  = (const float*)d_in[5];
    const float* v   = (const float*)d_in[6];
    float* out = (float*)d_out;

    cudaFuncSetAttribute(k2_scores, cudaFuncAttributeMaxDynamicSharedMemorySize,
                         SMTOT);

    k0_prep<<<NB_PREP, 256>>>(enc, w1, dec, w2, b1, b2);
    k2_scores<<<dim3(NTILES, 512), 256, SMTOT>>>(v);
    k3_softmax<<<32, 256>>>();
    k4_context<<<dim3(4, 32, NCHUNK), 256>>>();
    k5_reduce<<<128, 256>>>(out);
}

// round 15
// speedup vs baseline: 1.3737x; 1.0253x over previous
#include <cuda_runtime.h>
#include <cuda_fp16.h>
#include <math.h>
#include <stdint.h>

#define ENCD   1024
#define BATCH  32
#define SEQ    2048
#define MTOT   (BATCH * SEQ)   // 65536
#define NTILES 8               // 1024/128 n-tiles
#define NSTG   32              // K stages of 32
#define NCHUNK 16              // k4 S-chunks of 128

// Scratch (static device arrays: no allocation allowed).
__device__ __half g_ench[(size_t)MTOT * ENCD];   // fp16 copy of enc (128MB)
__device__ __half g_w1t[ENCD * ENCD];            // fp16 w1 TRANSPOSED [n][k]
__device__ float  g_q[BATCH * ENCD];
__device__ float  g_partials[NTILES * MTOT];
__device__ float  g_attn[MTOT];
__device__ float  g_ctx[NCHUNK][BATCH * ENCD];

// ---------------------------------------------------------------------------
__device__ __forceinline__ void mma_f16(float* d, const uint32_t* a, const uint32_t* b) {
    asm volatile(
        "mma.sync.aligned.m16n8k16.row.col.f32.f16.f16.f32 "
        "{%0,%1,%2,%3},{%4,%5,%6,%7},{%8,%9},{%0,%1,%2,%3};"
        : "+f"(d[0]), "+f"(d[1]), "+f"(d[2]), "+f"(d[3])
        : "r"(a[0]), "r"(a[1]), "r"(a[2]), "r"(a[3]), "r"(b[0]), "r"(b[1]));
}
#define LDSM4(r0, r1, r2, r3, addr)                                          \
    asm volatile("ldmatrix.sync.aligned.m8n8.x4.shared.b16 {%0,%1,%2,%3}, [%4];" \
                 : "=r"(r0), "=r"(r1), "=r"(r2), "=r"(r3) : "r"(addr))
__device__ __forceinline__ float tanh_fast(float x) {
    float xc = fminf(fmaxf(x, -9.0f), 9.0f);
    float y, r;
    asm("ex2.approx.f32 %0, %1;" : "=f"(y) : "f"(xc * 2.885390081777927f));
    asm("rcp.approx.f32 %0, %1;" : "=f"(r) : "f"(y + 1.0f));
    return (y - 1.0f) * r;
}
__device__ __forceinline__ uint32_t smem_u32(const void* p) {
    uint32_t a;
    asm("{ .reg .u64 t; cvta.to.shared.u64 t, %1; cvt.u32.u64 %0, t; }"
        : "=r"(a) : "l"(p));
    return a;
}
#define CP_ASYNC16(dst, src) \
    asm volatile("cp.async.cg.shared.global [%0], [%1], 16;" :: "r"(dst), "l"(src) : "memory")
#define CP_COMMIT()  asm volatile("cp.async.commit_group;" ::: "memory")
#define CP_WAIT2()   asm volatile("cp.async.wait_group 2;" ::: "memory")

// smem geometry (bytes). A stage: 128 m-rows x 80B (64B = 32 fp16 + 16B pad).
// B stage: 128 n-rows x 80B. 80B stride -> each 8-lane ldmatrix phase hits
// all 32 banks exactly once. 4-stage ring.
#define ASTG   10240
#define BSTG   10240
#define OFF_A  0
#define OFF_B  (4 * ASTG)            // 40960
#define OFF_QS (OFF_B + 4 * BSTG)    // 81920
#define OFF_VS (OFF_QS + 512)
#define OFF_SR (OFF_VS + 512)
#define SMTOT  (OFF_SR + 2048)       // 84992

// Fused prep kernel block ranges.
#define NB_Q   128                   // query blocks (4 e-chunks x 32 batches)
#define NB_W1T 1024                  // w1 transpose blocks (32 x 32 tiles)
#define NB_ENC 32768                 // enc convert blocks
#define NB_PREP (NB_Q + NB_W1T + NB_ENC)

// ---------------------------------------------------------------------------
// K0: fused prep (query GEMV | w1 transpose->fp16 | enc->fp16).
// ---------------------------------------------------------------------------
__global__ __launch_bounds__(256)
void k0_prep(const float* __restrict__ enc, const float* __restrict__ w1,
             const float* __restrict__ dec, const float* __restrict__ w2,
             const float* __restrict__ b1, const float* __restrict__ b2) {
    __shared__ float sh[1056];
    const int id = blockIdx.x;
    const int t  = threadIdx.x;

    if (id < NB_Q) {
        const int bx = id & 3, b = id >> 2;
        for (int i = t; i < ENCD; i += 256) sh[i] = dec[b * ENCD + i];
        __syncthreads();
        const int e = bx * 256 + t;
        float acc = 0.f;
        #pragma unroll 8
        for (int d = 0; d < ENCD; d++)
            acc += sh[d] * w2[(size_t)d * ENCD + e];
        g_q[b * ENCD + e] = acc + b1[e] + b2[e];
    } else if (id < NB_Q + NB_W1T) {
        const int tid = id - NB_Q;
        const int nb = (tid & 31) * 32, k0 = (tid >> 5) * 32;
        float (*tl)[33] = (float(*)[33])sh;
        const int tx = t & 31, ty = t >> 5;
        #pragma unroll
        for (int i = 0; i < 32; i += 8)
            tl[ty + i][tx] = w1[(size_t)(k0 + ty + i) * ENCD + nb + tx];
        __syncthreads();
        #pragma unroll
        for (int i = 0; i < 32; i += 8)
            g_w1t[(size_t)(nb + ty + i) * ENCD + k0 + tx] =
                __float2half_rn(tl[tx][ty + i]);
    } else {
        const size_t i = ((size_t)(id - NB_Q - NB_W1T) * 256 + t) * 8;
        float4 f0 = *(const float4*)(enc + i);
        float4 f1 = *(const float4*)(enc + i + 4);
        __half2 h0 = __floats2half2_rn(f0.x, f0.y);
        __half2 h1 = __floats2half2_rn(f0.z, f0.w);
        __half2 h2 = __floats2half2_rn(f1.x, f1.y);
        __half2 h3 = __floats2half2_rn(f1.z, f1.w);
        uint4 u;
        u.x = *(uint32_t*)&h0; u.y = *(uint32_t*)&h1;
        u.z = *(uint32_t*)&h2; u.w = *(uint32_t*)&h3;
        *(uint4*)(g_ench + i) = u;
    }
}

// ---------------------------------------------------------------------------
// K2: fused score GEMM, fp16 mma.sync m16n8k16 + ldmatrix.x4 fragments,
// cp.async 4-stage pipeline (R11 configuration — best measured).
// CTA tile 128x128, 8 warps 2(M)x4(N), warp 64x32. grid (8, 512), 256 thr.
// ---------------------------------------------------------------------------
__global__ __launch_bounds__(256, 2)
void k2_scores(const float* __restrict__ v) {
    extern __shared__ __align__(16) float smf[];
    const uint32_t sb = smem_u32(smf);
    float* qs   = smf + (OFF_QS >> 2);
    float* vs   = smf + (OFF_VS >> 2);
    float* sred = smf + (OFF_SR >> 2);

    const int nt = blockIdx.x, n0 = nt * 128;
    const int m0 = blockIdx.y * 128;
    const int b  = m0 / SEQ;
    const int t  = threadIdx.x;
    const int lane = t & 31, w = t >> 5;
    const int wm = w & 1, wn = w >> 1;
    const int g = lane >> 2, c = lane & 3;

    if (t < 128) { qs[t] = g_q[b * ENCD + n0 + t]; vs[t] = v[n0 + t]; }

    const int lrow  = ((lane >> 3) & 1) * 8 + (lane & 7);
    const int lkoff = (lane >> 4) * 16;
    const uint32_t aTile = sb + OFF_A + (wm * 64 + lrow) * 80 + lkoff;
    const uint32_t bTile = sb + OFF_B + (wn * 32 + lrow) * 80 + lkoff;

    const int r0 = t >> 2, r1 = r0 + 64, j = t & 3;
    const __half* aS0 = g_ench + (size_t)(m0 + r0) * ENCD + j * 8;
    const __half* aS1 = g_ench + (size_t)(m0 + r1) * ENCD + j * 8;
    const __half* bS0 = g_w1t + (size_t)(n0 + r0) * ENCD + j * 8;
    const __half* bS1 = g_w1t + (size_t)(n0 + r1) * ENCD + j * 8;
    const uint32_t aD0 = sb + OFF_A + r0 * 80 + j * 16;
    const uint32_t aD1 = sb + OFF_A + r1 * 80 + j * 16;
    const uint32_t bD0 = sb + OFF_B + r0 * 80 + j * 16;
    const uint32_t bD1 = sb + OFF_B + r1 * 80 + j * 16;

    #define ISSUE(s)                                                         \
        do {                                                                 \
            const uint32_t _rb = ((s) & 3) * ASTG;                           \
            const int _ko = (s) * 32;                                        \
            CP_ASYNC16(aD0 + _rb, aS0 + _ko);                                \
            CP_ASYNC16(aD1 + _rb, aS1 + _ko);                                \
            CP_ASYNC16(bD0 + _rb, bS0 + _ko);                                \
            CP_ASYNC16(bD1 + _rb, bS1 + _ko);                                \
        } while (0)

    float acc[4][4][4];
    #pragma unroll
    for (int mi = 0; mi < 4; mi++)
        #pragma unroll
        for (int ni = 0; ni < 4; ni++)
            #pragma unroll
            for (int r = 0; r < 4; r++) acc[mi][ni][r] = 0.f;

    ISSUE(0); CP_COMMIT();
    ISSUE(1); CP_COMMIT();

    for (int s = 0; s < NSTG; s++) {
        if (s + 2 < NSTG) ISSUE(s + 2);
        CP_COMMIT();
        CP_WAIT2();
        __syncthreads();

        const uint32_t stg = (s & 3) * ASTG;
        #pragma unroll
        for (int kh = 0; kh < 2; kh++) {
            const uint32_t kb = stg + kh * 32;
            uint32_t af[4][4], bf[4][2];
            #pragma unroll
            for (int mi = 0; mi < 4; mi++)
                LDSM4(af[mi][0], af[mi][1], af[mi][2], af[mi][3],
                      aTile + mi * 1280 + kb);
            LDSM4(bf[0][0], bf[1][0], bf[0][1], bf[1][1], bTile + kb);
            LDSM4(bf[2][0], bf[3][0], bf[2][1], bf[3][1], bTile + 1280 + kb);
            #pragma unroll
            for (int mi = 0; mi < 4; mi++)
                #pragma unroll
                for (int ni = 0; ni < 4; ni++)
                    mma_f16(acc[mi][ni], af[mi], bf[ni]);
        }
    }

    float rs0[4], rs1[4];
    #pragma unroll
    for (int mi = 0; mi < 4; mi++) {
        float s0 = 0.f, s1 = 0.f;
        #pragma unroll
        for (int ni = 0; ni < 4; ni++) {
            const int n_ = wn * 32 + ni * 8 + c * 2;
            const float q0 = qs[n_], q1 = qs[n_ + 1];
            const float v0 = vs[n_], v1 = vs[n_ + 1];
            s0 += tanh_fast(acc[mi][ni][0] + q0) * v0
                + tanh_fast(acc[mi][ni][1] + q1) * v1;
            s1 += tanh_fast(acc[mi][ni][2] + q0) * v0
                + tanh_fast(acc[mi][ni][3] + q1) * v1;
        }
        s0 += __shfl_xor_sync(0xffffffffu, s0, 1);
        s0 += __shfl_xor_sync(0xffffffffu, s0, 2);
        s1 += __shfl_xor_sync(0xffffffffu, s1, 1);
        s1 += __shfl_xor_sync(0xffffffffu, s1, 2);
        rs0[mi] = s0; rs1[mi] = s1;
    }
    if (c == 0) {
        #pragma unroll
        for (int mi = 0; mi < 4; mi++) {
            sred[wn * 128 + wm * 64 + mi * 16 + g]     = rs0[mi];
            sred[wn * 128 + wm * 64 + mi * 16 + g + 8] = rs1[mi];
        }
    }
    __syncthreads();
    if (t < 128)
        g_partials[(size_t)nt * MTOT + m0 + t] =
            (sred[t] + sred[128 + t]) + (sred[256 + t] + sred[384 + t]);
}

// ---------------------------------------------------------------------------
// K3: sum NTILES partials (fixed order), softmax over S per batch.
// ---------------------------------------------------------------------------
__global__ __launch_bounds__(256)
void k3_softmax() {
    __shared__ float red[256];
    const int b = blockIdx.x, t = threadIdx.x;
    float sc[8];
    float mx = -1e30f;
    #pragma unroll
    for (int i = 0; i < 8; i++) {
        const int s = t + 256 * i;
        float v0 = 0.f;
        #pragma unroll
        for (int nt = 0; nt < NTILES; nt++)
            v0 += g_partials[(size_t)nt * MTOT + b * SEQ + s];
        sc[i] = v0;
        mx = fmaxf(mx, v0);
    }
    red[t] = mx; __syncthreads();
    for (int o = 128; o > 0; o >>= 1) {
        if (t < o) red[t] = fmaxf(red[t], red[t + o]);
        __syncthreads();
    }
    mx = red[0]; __syncthreads();
    float sum = 0.f;
    #pragma unroll
    for (int i = 0; i < 8; i++) { sc[i] = expf(sc[i] - mx); sum += sc[i]; }
    red[t] = sum; __syncthreads();
    for (int o = 128; o > 0; o >>= 1) {
        if (t < o) red[t] += red[t + o];
        __syncthreads();
    }
    const float inv = 1.f / red[0];
    #pragma unroll
    for (int i = 0; i < 8; i++)
        g_attn[b * SEQ + t + 256 * i] = sc[i] * inv;
}

// ---------------------------------------------------------------------------
// K4: partial context over S-chunks of 128, half2 e-pairs.
// grid (2, 32, 16), 256 thr: thread owns e = bx*512 + t*2 (+1).
// ---------------------------------------------------------------------------
__global__ __launch_bounds__(256)
void k4_context() {
    __shared__ float sat[128];
    const int b  = blockIdx.y;
    const int sc = blockIdx.z;
    const int t  = threadIdx.x;
    const int e0 = blockIdx.x * 512 + t * 2;
    const int sbase = sc * 128;
    if (t < 128) sat[t] = g_attn[b * SEQ + sbase + t];
    __syncthreads();
    const uint32_t* ep = (const uint32_t*)
        (g_ench + ((size_t)b * SEQ + sbase) * ENCD + e0);
    float ax0 = 0, ay0 = 0, ax1 = 0, ay1 = 0, ax2 = 0, ay2 = 0, ax3 = 0, ay3 = 0;
    float ax4 = 0, ay4 = 0, ax5 = 0, ay5 = 0, ax6 = 0, ay6 = 0, ax7 = 0, ay7 = 0;
    #define K4STEP(i, AX, AY)                                                 \
        do {                                                                  \
            uint32_t u = ep[(size_t)(s + i) * (ENCD / 2)];                    \
            float2 f = __half22float2(*(__half2*)&u);                         \
            AX += sat[s + i] * f.x; AY += sat[s + i] * f.y;                   \
        } while (0)
    for (int s = 0; s < 128; s += 8) {
        K4STEP(0, ax0, ay0); K4STEP(1, ax1, ay1);
        K4STEP(2, ax2, ay2); K4STEP(3, ax3, ay3);
        K4STEP(4, ax4, ay4); K4STEP(5, ax5, ay5);
        K4STEP(6, ax6, ay6); K4STEP(7, ax7, ay7);
    }
    g_ctx[sc][b * ENCD + e0]     = ((ax0 + ax1) + (ax2 + ax3)) + ((ax4 + ax5) + (ax6 + ax7));
    g_ctx[sc][b * ENCD + e0 + 1] = ((ay0 + ay1) + (ay2 + ay3)) + ((ay4 + ay5) + (ay6 + ay7));
}

__global__ __launch_bounds__(256)
void k5_reduce(float* __restrict__ out) {
    const int i = blockIdx.x * 256 + threadIdx.x;
    float s = 0.f;
    #pragma unroll
    for (int ch = 0; ch < NCHUNK; ch++) s += g_ctx[ch][i];
    out[i] = s;
}

// ---------------------------------------------------------------------------
extern "C" void kernel_launch(void* const* d_in, const int* in_sizes, int n_in,
                              void* d_out, int out_size) {
    const float* enc = (const float*)d_in[0];
    const float* dec = (const float*)d_in[1];
    const float* w1  = (const float*)d_in[2];
    const float* b1  = (const float*)d_in[3];
    const float* w2  = (const float*)d_in[4];
    const float* b2  = (const float*)d_in[5];
    const float* v   = (const float*)d_in[6];
    float* out = (float*)d_out;

    cudaFuncSetAttribute(k2_scores, cudaFuncAttributeMaxDynamicSharedMemorySize,
                         SMTOT);

    k0_prep<<<NB_PREP, 256>>>(enc, w1, dec, w2, b1, b2);
    k2_scores<<<dim3(NTILES, 512), 256, SMTOT>>>(v);
    k3_softmax<<<32, 256>>>();
    k4_context<<<dim3(2, 32, NCHUNK), 256>>>();
    k5_reduce<<<128, 256>>>(out);
}